// round 15
// baseline (speedup 1.0000x reference)
#include <cuda_runtime.h>
#include <cuda_bf16.h>
#include <cstdint>

// ---------------------------------------------------------------------------
// MGMQTorchModel R15 (= R13 fused kernel + k2 at 512 threads for occupancy):
//   fused : GAT -> shuffle-pack bf16 hi/lo into smem A images (B kc0
//           prefetch overlapped) -> HMMA GEMM -> bias+elu+mean -> scatter.
//   k2    : proj + gi + block GRU + out, 8 batches per 512-thread block.
// ---------------------------------------------------------------------------

#define NB 8192
#define NODES (NB*5)          // 40960
#define NTILES (NODES/8)      // 5120 (8 nodes x 12 rows = M 96)

__device__ float g_nbr_emb[NB * 4 * 128];
__device__ __nv_bfloat16 g_WtT[2 * 32768];   // [term][n 128][k 256]
__device__ float g_Wa[64];                   // [s][src/dst][h][f]

__device__ __forceinline__ float tanh_fast(float x) {
    float y; asm("tanh.approx.f32 %0, %1;" : "=f"(y) : "f"(x)); return y;
}
__device__ __forceinline__ float sigmoid_fast(float x) {
    return 1.f / (1.f + __expf(-x));
}
__device__ __forceinline__ float elu_f(float x) {
    return (x > 0.f) ? x : (__expf(x) - 1.f);
}
__device__ __forceinline__ uint32_t smem_u32(const void* p) {
    uint32_t a;
    asm("{ .reg .u64 t; cvta.to.shared.u64 t, %1; cvt.u32.u64 %0, t; }" : "=r"(a) : "l"(p));
    return a;
}
__device__ __forceinline__ void mma16816(float* d, const uint32_t* a,
                                         uint32_t b0, uint32_t b1) {
    asm volatile(
        "mma.sync.aligned.m16n8k16.row.col.f32.bf16.bf16.f32 "
        "{%0,%1,%2,%3}, {%4,%5,%6,%7}, {%8,%9}, {%0,%1,%2,%3};"
        : "+f"(d[0]), "+f"(d[1]), "+f"(d[2]), "+f"(d[3])
        : "r"(a[0]), "r"(a[1]), "r"(a[2]), "r"(a[3]), "r"(b0), "r"(b1));
}
#define LDSM_X4(r, addr) \
    asm volatile("ldmatrix.sync.aligned.m8n8.x4.shared.b16 {%0,%1,%2,%3}, [%4];" \
        : "=r"((r)[0]), "=r"((r)[1]), "=r"((r)[2]), "=r"((r)[3]) : "r"(addr))
#define GBAR(id) \
    asm volatile("bar.sync %0, 128;" :: "r"((id) + 1) : "memory")

// ======================= setup: W_fuse -> Wt images + Wa ====================
__global__ void mgmq_wsplit(const float* __restrict__ W_fuse,
                            const float* __restrict__ W_coop,
                            const float* __restrict__ a_src_coop,
                            const float* __restrict__ a_dst_coop,
                            const float* __restrict__ W_conf,
                            const float* __restrict__ a_src_conf,
                            const float* __restrict__ a_dst_conf) {
    int idx = blockIdx.x * blockDim.x + threadIdx.x;
    if (blockIdx.x == 0 && threadIdx.x < 64) {
        int i = threadIdx.x;
        int s = i >> 5, v = (i >> 4) & 1, h = (i >> 2) & 3, f = i & 3;
        const float* W = s ? W_conf : W_coop;
        const float* a = s ? (v ? a_dst_conf : a_src_conf)
                           : (v ? a_dst_coop : a_src_coop);
        float acc = 0.f;
        #pragma unroll
        for (int o = 0; o < 32; o++)
            acc += __ldg(&W[(h * 4 + f) * 32 + o]) * __ldg(&a[h * 32 + o]);
        g_Wa[i] = acc;
    }
    if (idx >= 128 * 256) return;
    int n = idx >> 8;
    int k = idx & 255;
    float w = W_fuse[k * 128 + n];
    __nv_bfloat16 hi = __float2bfloat16(w);
    __nv_bfloat16 lo = __float2bfloat16(w - __bfloat162float(hi));
    g_WtT[n * 256 + k] = hi;
    g_WtT[32768 + n * 256 + k] = lo;
}

// ======================== FUSED kernel (R13, unchanged) =====================
#define A_RS    528
#define AHI_OFF 0
#define ALO_OFF 50688
#define X_OFF   101376
#define B_IMG   34816
#define SW_OFF  171008
#define SX_OFF  175104
#define ATTC_OFF 176640
#define ATTF_OFF 179712
#define BIAS_OFF 188928
#define SMEM_FUSED 189440
#define CH_RS   272

__global__ __launch_bounds__(512) void mgmq_fused(
    const float* __restrict__ self_f, const float* __restrict__ nbr_f,
    const float* __restrict__ W_coop, const float* __restrict__ W_conf,
    const float* __restrict__ b_fuse, float* __restrict__ out)
{
    extern __shared__ char dsm[];
    float* sW   = (float*)(dsm + SW_OFF);
    float* sx   = (float*)(dsm + SX_OFF);
    float4* sAttC = (float4*)(dsm + ATTC_OFF);
    float*  sAttF = (float*)(dsm + ATTF_OFF);
    float* sbias = (float*)(dsm + BIAS_OFF);

    const int t = threadIdx.x;
    const int wid = t >> 5;
    const int lid = t & 31;
    const int tile = blockIdx.x;

    const uint4* gBH = (const uint4*)g_WtT;
    const uint4* gBL = (const uint4*)(g_WtT + 32768);

    if (t < 128) ((float4*)sW)[t] = __ldg(&((const float4*)W_coop)[t]);
    else if (t < 256) ((float4*)sW)[t] = __ldg(&((const float4*)W_conf)[t - 128]);
    if (t >= 384) sbias[t - 384] = __ldg(&b_fuse[t - 384]);
    if (t < 384) {
        int n8 = t / 48, f = t % 48;
        int node = tile * 8 + n8;
        int b = node / 5, slot = node - b * 5;
        const float* xsrc = (slot == 0) ? (self_f + (size_t)b * 48)
                                        : (nbr_f + ((size_t)b * 4 + (slot - 1)) * 48);
        sx[n8 * 48 + f] = __ldg(&xsrc[f]);
    }

    for (int i = t; i < 4096; i += 512) {
        int term = i >> 11;
        int r = i & 2047;
        int nr = r >> 4, c16 = r & 15;
        const uint4* gB = term ? gBL : gBH;
        *(uint4*)(dsm + X_OFF + term * B_IMG + nr * CH_RS + c16 * 16)
            = gB[nr * 32 + c16];
    }
    __syncthreads();

    const int nl = t >> 7;
    const int tt = t & 127;
    const int o = tt & 31, h = tt >> 5;
    const int opair2 = (o & ~1) * 2;
    const bool evn = (o & 1) == 0;

    #pragma unroll
    for (int p = 0; p < 2; p++) {
        const int n8 = p * 4 + nl;
        const float* nx = sx + n8 * 48;

        if (tt < 48) {
            int hh = tt / 12, i = tt - hh * 12, j0 = (i / 3) * 3;
            float was0 = __ldg(&g_Wa[hh*4+0]), was1 = __ldg(&g_Wa[hh*4+1]);
            float was2 = __ldg(&g_Wa[hh*4+2]), was3 = __ldg(&g_Wa[hh*4+3]);
            float wad0 = __ldg(&g_Wa[16+hh*4+0]), wad1 = __ldg(&g_Wa[16+hh*4+1]);
            float wad2 = __ldg(&g_Wa[16+hh*4+2]), wad3 = __ldg(&g_Wa[16+hh*4+3]);
            float es = nx[i*4]*was0 + nx[i*4+1]*was1 + nx[i*4+2]*was2 + nx[i*4+3]*was3;
            float e[3];
            #pragma unroll
            for (int jj = 0; jj < 3; jj++) {
                int j = j0 + jj;
                float ed = nx[j*4]*wad0 + nx[j*4+1]*wad1 + nx[j*4+2]*wad2 + nx[j*4+3]*wad3;
                float v = es + ed;
                e[jj] = (v > 0.f) ? v : 0.2f * v;
            }
            float m = fmaxf(e[0], fmaxf(e[1], e[2]));
            float x0 = __expf(e[0]-m), x1 = __expf(e[1]-m), x2 = __expf(e[2]-m);
            float inv = 1.f / (x0 + x1 + x2);
            sAttC[(nl * 4 + hh) * 12 + i] = make_float4(x0*inv, x1*inv, x2*inv, 0.f);
        } else if (tt < 96) {
            int r = tt - 48;
            int hh = r / 12, i = r - hh * 12;
            int gi = i / 3;
            float was0 = __ldg(&g_Wa[32+hh*4+0]), was1 = __ldg(&g_Wa[32+hh*4+1]);
            float was2 = __ldg(&g_Wa[32+hh*4+2]), was3 = __ldg(&g_Wa[32+hh*4+3]);
            float wad0 = __ldg(&g_Wa[48+hh*4+0]), wad1 = __ldg(&g_Wa[48+hh*4+1]);
            float wad2 = __ldg(&g_Wa[48+hh*4+2]), wad3 = __ldg(&g_Wa[48+hh*4+3]);
            float es = nx[i*4]*was0 + nx[i*4+1]*was1 + nx[i*4+2]*was2 + nx[i*4+3]*was3;
            float ev[12], m = -1e30f;
            #pragma unroll
            for (int j = 0; j < 12; j++) {
                float ed = nx[j*4]*wad0 + nx[j*4+1]*wad1 + nx[j*4+2]*wad2 + nx[j*4+3]*wad3;
                float e = es + ed;
                e = (e > 0.f) ? e : 0.2f * e;
                bool valid = ((j / 3) != gi);
                ev[j] = valid ? e : -1e30f;
                if (valid && e > m) m = e;
            }
            float sum = 0.f, ex[12];
            #pragma unroll
            for (int j = 0; j < 12; j++) {
                float v = (ev[j] > -1e29f) ? __expf(ev[j] - m) : 0.f;
                ex[j] = v; sum += v;
            }
            float inv = 1.f / sum;
            #pragma unroll
            for (int j = 0; j < 12; j++)
                sAttF[((nl * 4 + hh) * 12 + i) * 12 + j] = ex[j] * inv;
        }

        float wh0[12], wh1[12];
        {
            float w00 = sW[h*128 +  0 + o], w01 = sW[h*128 + 32 + o];
            float w02 = sW[h*128 + 64 + o], w03 = sW[h*128 + 96 + o];
            float w10 = sW[512 + h*128 +  0 + o], w11 = sW[512 + h*128 + 32 + o];
            float w12 = sW[512 + h*128 + 64 + o], w13 = sW[512 + h*128 + 96 + o];
            #pragma unroll
            for (int j = 0; j < 12; j++) {
                float x0 = nx[j*4], x1 = nx[j*4+1], x2 = nx[j*4+2], x3 = nx[j*4+3];
                wh0[j] = x0*w00 + x1*w01 + x2*w02 + x3*w03;
                wh1[j] = x0*w10 + x1*w11 + x2*w12 + x3*w13;
            }
        }
        GBAR(nl);

        {
            const int rbase = n8 * 12;
            #pragma unroll
            for (int i = 0; i < 12; i++) {
                const int j0 = (i / 3) * 3;
                float4 a = sAttC[(nl * 4 + h) * 12 + i];
                float vc = elu_f(a.x * wh0[j0] + a.y * wh0[j0+1] + a.z * wh0[j0+2]);
                const float* ar = sAttF + ((nl * 4 + h) * 12 + i) * 12;
                float accf = 0.f;
                #pragma unroll
                for (int j = 0; j < 12; j++)
                    if (j < j0 || j >= j0 + 3) accf += ar[j] * wh1[j];
                float vf = elu_f(accf);

                const uint32_t rowoff = (uint32_t)(rbase + i) * A_RS;
                {
                    __nv_bfloat16 hb = __float2bfloat16(vc);
                    float rr = vc - __bfloat162float(hb);
                    __nv_bfloat16 lb = __float2bfloat16(rr);
                    uint32_t hu = (uint32_t)__bfloat16_as_ushort(hb);
                    uint32_t lu = (uint32_t)__bfloat16_as_ushort(lb);
                    uint32_t ho = __shfl_xor_sync(0xFFFFFFFFu, hu, 1);
                    uint32_t lo = __shfl_xor_sync(0xFFFFFFFFu, lu, 1);
                    uint32_t boff = rowoff + (uint32_t)(h * 64) + opair2;
                    if (evn) *(uint32_t*)(dsm + AHI_OFF + boff) = hu | (ho << 16);
                    else     *(uint32_t*)(dsm + ALO_OFF + boff) = lo | (lu << 16);
                }
                {
                    __nv_bfloat16 hb = __float2bfloat16(vf);
                    float rr = vf - __bfloat162float(hb);
                    __nv_bfloat16 lb = __float2bfloat16(rr);
                    uint32_t hu = (uint32_t)__bfloat16_as_ushort(hb);
                    uint32_t lu = (uint32_t)__bfloat16_as_ushort(lb);
                    uint32_t ho = __shfl_xor_sync(0xFFFFFFFFu, hu, 1);
                    uint32_t lo = __shfl_xor_sync(0xFFFFFFFFu, lu, 1);
                    uint32_t boff = rowoff + 256u + (uint32_t)(h * 64) + opair2;
                    if (evn) *(uint32_t*)(dsm + AHI_OFF + boff) = hu | (ho << 16);
                    else     *(uint32_t*)(dsm + ALO_OFF + boff) = lo | (lu << 16);
                }
            }
        }
        GBAR(nl);
    }
    __syncthreads();

    const int mtile = wid >> 1;
    const int nhalf = wid & 1;
    const int g = lid >> 2;
    const int q = lid & 3;
    const int row0 = mtile * 16 + g;
    const int row1 = row0 + 8;
    const bool mma_w = (wid < 12);

    const uint32_t sbase = smem_u32(dsm);
    const uint32_t a_lane = (uint32_t)((mtile * 16 + ((lid >> 3) & 1) * 8 + (lid & 7)) * A_RS
                          + ((lid >> 4) & 1) * 16);
    const uint32_t b_lane = (uint32_t)((nhalf * 64 + ((lid >> 4) & 1) * 8 + (lid & 7)) * CH_RS
                          + ((lid >> 3) & 1) * 16);

    float d[8][4];
    #pragma unroll
    for (int nt = 0; nt < 8; nt++) {
        d[nt][0] = 0.f; d[nt][1] = 0.f; d[nt][2] = 0.f; d[nt][3] = 0.f;
    }

    #pragma unroll
    for (int kc = 0; kc < 2; kc++) {
        if (kc == 1) {
            for (int i = t; i < 4096; i += 512) {
                int term = i >> 11;
                int r = i & 2047;
                int nr = r >> 4, c16 = r & 15;
                const uint4* gB = term ? gBL : gBH;
                *(uint4*)(dsm + X_OFF + term * B_IMG + nr * CH_RS + c16 * 16)
                    = gB[nr * 32 + 16 + c16];
            }
            __syncthreads();
        }

        if (mma_w) {
            const uint32_t aHb = sbase + AHI_OFF + a_lane + kc * 256;
            const uint32_t aLb = sbase + ALO_OFF + a_lane + kc * 256;
            const uint32_t bHb = sbase + X_OFF + b_lane;
            const uint32_t bLb = sbase + X_OFF + B_IMG + b_lane;

            #pragma unroll
            for (int ks = 0; ks < 8; ks++) {
                const uint32_t koff = ks * 32;
                uint32_t ah[4], al[4];
                LDSM_X4(ah, aHb + koff);
                LDSM_X4(al, aLb + koff);
                #pragma unroll
                for (int pp = 0; pp < 4; pp++) {
                    uint32_t bh[4], bl[4];
                    LDSM_X4(bh, bHb + pp * (16 * CH_RS) + koff);
                    LDSM_X4(bl, bLb + pp * (16 * CH_RS) + koff);
                    mma16816(d[2*pp],     ah, bh[0], bh[1]);
                    mma16816(d[2*pp],     ah, bl[0], bl[1]);
                    mma16816(d[2*pp],     al, bh[0], bh[1]);
                    mma16816(d[2*pp + 1], ah, bh[2], bh[3]);
                    mma16816(d[2*pp + 1], ah, bl[2], bl[3]);
                    mma16816(d[2*pp + 1], al, bh[2], bh[3]);
                }
            }
        }
        __syncthreads();
    }

    float* Dbuf = (float*)(dsm + X_OFF);
    if (mma_w) {
        #pragma unroll
        for (int nt = 0; nt < 8; nt++) {
            int c0 = nhalf * 64 + nt * 8 + q * 2;
            float b0 = sbias[c0], b1 = sbias[c0 + 1];
            float2 v0 = make_float2(elu_f(d[nt][0] + b0), elu_f(d[nt][1] + b1));
            float2 v1 = make_float2(elu_f(d[nt][2] + b0), elu_f(d[nt][3] + b1));
            *(float2*)&Dbuf[row0 * 132 + c0] = v0;
            *(float2*)&Dbuf[row1 * 132 + c0] = v1;
        }
    }
    __syncthreads();

    if (t < 256) {
        int nl8 = t >> 5;
        int c4 = (t & 31) << 2;
        float4 s = make_float4(0.f, 0.f, 0.f, 0.f);
        #pragma unroll
        for (int j = 0; j < 12; j++) {
            float4 v = *(const float4*)&Dbuf[(nl8 * 12 + j) * 132 + c4];
            s.x += v.x; s.y += v.y; s.z += v.z; s.w += v.w;
        }
        s.x *= (1.f/12.f); s.y *= (1.f/12.f); s.z *= (1.f/12.f); s.w *= (1.f/12.f);
        int node = tile * 8 + nl8;
        int b = node / 5, slot = node - b * 5;
        if (slot == 0) *(float4*)&out[(size_t)b * 192 + c4] = s;
        else *(float4*)&g_nbr_emb[((size_t)b * 4 + (slot - 1)) * 128 + c4] = s;
    }
}

// ============================ KERNEL 2 ======================================
// 8 batches per 512-thread block (occupancy: 3 CTAs x 16 warps = 48 warps/SM)
struct K2Smem {
    float nbr[8][4][132];
    float x[8][4][64];
    float gi[8][2][4][96];
    float gh[8][2][96];
    float h[8][2][32];
    float cat[8][192];
};
#define SMEM_K2 ((int)sizeof(K2Smem))

__global__ __launch_bounds__(512) void mgmq_k2(
    const float* __restrict__ mask, const float* __restrict__ dirs,
    const float* __restrict__ W_proj, const float* __restrict__ b_proj,
    const float* __restrict__ Wih_f, const float* __restrict__ Whh_f,
    const float* __restrict__ bih_f, const float* __restrict__ bhh_f,
    const float* __restrict__ Wih_b, const float* __restrict__ Whh_b,
    const float* __restrict__ bih_b, const float* __restrict__ bhh_b,
    const float* __restrict__ W_out, const float* __restrict__ b_out,
    float* __restrict__ out)
{
    extern __shared__ char k2dsm[];
    K2Smem* S = (K2Smem*)k2dsm;
    const int b0 = blockIdx.x * 8;
    const int t = threadIdx.x;

    for (int i = t; i < 1024; i += 512) {
        int bb = i >> 7, kk = (i >> 5) & 3, c4 = (i & 31) << 2;
        *(float4*)&S->nbr[bb][kk][c4] =
            *(const float4*)&g_nbr_emb[(((size_t)(b0 + bb)) * 4 + kk) * 128 + c4];
    }
    if (t < 32) S->nbr[t >> 2][t & 3][128] = dirs[(b0 + (t >> 2)) * 4 + (t & 3)];
    if (t < 256) {
        int bb = t >> 5, c4 = (t & 31) << 2;
        *(float4*)&S->cat[bb][c4] = *(const float4*)&out[(size_t)(b0 + bb) * 192 + c4];
    }
    {   // h init: 512 = 8 bb x 2 d x 32 g
        int bb = t >> 6, d = (t >> 5) & 1, g = t & 31;
        S->h[bb][d][g] = 0.f;
    }
    __syncthreads();

    // proj: 512 threads = 64 (kk,j4) combos x 8 batches, one batch each
    {
        int combo = t & 63, bb = t >> 6;
        int kk = combo >> 4, j4 = (combo & 15) << 2;
        float4 acc = __ldg((const float4*)&b_proj[j4]);
        #pragma unroll 4
        for (int i = 0; i < 129; i++) {
            float4 w = __ldg((const float4*)&W_proj[i * 64 + j4]);
            float xv = S->nbr[bb][kk][i];
            acc.x += xv*w.x; acc.y += xv*w.y; acc.z += xv*w.z; acc.w += xv*w.w;
        }
        float m = mask[(b0 + bb) * 4 + kk];
        acc.x = (acc.x > 0.f ? acc.x : 0.f) * m;
        acc.y = (acc.y > 0.f ? acc.y : 0.f) * m;
        acc.z = (acc.z > 0.f ? acc.z : 0.f) * m;
        acc.w = (acc.w > 0.f ? acc.w : 0.f) * m;
        *(float4*)&S->x[bb][kk][j4] = acc;
    }
    __syncthreads();

    // gi: 384 threads = (d, kk, j4-quad) x 2 batch-quads of 4
    if (t < 384) {
        int half = t / 192, r = t % 192;
        int d = r / 96, rr = r % 96, kk = rr / 24, j4 = (rr % 24) << 2;
        const float* Wih = d ? Wih_b : Wih_f;
        const float* bih = d ? bih_b : bih_f;
        float4 bs = __ldg((const float4*)&bih[j4]);
        float4 acc[4];
        #pragma unroll
        for (int bi = 0; bi < 4; bi++) acc[bi] = bs;
        for (int i = 0; i < 64; i++) {
            float4 w = __ldg((const float4*)&Wih[i * 96 + j4]);
            #pragma unroll
            for (int bi = 0; bi < 4; bi++) {
                float xv = S->x[half * 4 + bi][kk][i];
                acc[bi].x += xv*w.x; acc[bi].y += xv*w.y;
                acc[bi].z += xv*w.z; acc[bi].w += xv*w.w;
            }
        }
        #pragma unroll
        for (int bi = 0; bi < 4; bi++)
            *(float4*)&S->gi[half * 4 + bi][d][kk][j4] = acc[bi];
    }
    __syncthreads();

    // GRU: 4 steps, block-synchronous
    for (int step = 0; step < 4; step++) {
        if (t < 384) {
            int combo = t % 48, bb = t / 48;
            int d = combo / 24, j4 = (combo % 24) << 2;
            const float* Whh = d ? Whh_b : Whh_f;
            const float* bhh = d ? bhh_b : bhh_f;
            float4 acc = __ldg((const float4*)&bhh[j4]);
            #pragma unroll
            for (int i = 0; i < 32; i++) {
                float hv = S->h[bb][d][i];
                float4 w = __ldg((const float4*)&Whh[i * 96 + j4]);
                acc.x += hv*w.x; acc.y += hv*w.y; acc.z += hv*w.z; acc.w += hv*w.w;
            }
            *(float4*)&S->gh[bb][d][j4] = acc;
        }
        __syncthreads();
        {
            int bb = t >> 6, d = (t >> 5) & 1, g = t & 31;
            int kf = d ? (3 - step) : step;
            float r = sigmoid_fast(S->gi[bb][d][kf][g]      + S->gh[bb][d][g]);
            float z = sigmoid_fast(S->gi[bb][d][kf][32 + g] + S->gh[bb][d][32 + g]);
            float nn = tanh_fast(S->gi[bb][d][kf][64 + g] + r * S->gh[bb][d][64 + g]);
            S->h[bb][d][g] = (1.f - z) * nn + z * S->h[bb][d][g];
        }
        __syncthreads();
    }

    {   // concat h: 512 = 8 bb x 64
        int bb = t >> 6, r = t & 63;
        S->cat[bb][128 + r] = S->h[bb][r >> 5][r & 31];
    }
    __syncthreads();

    // out: 128 threads (8 bb x 16 j4-quads)
    if (t < 128) {
        int bb = t >> 4, j4 = (t & 15) << 2;
        float4 acc = __ldg((const float4*)&b_out[j4]);
        #pragma unroll 4
        for (int i = 0; i < 192; i++) {
            float cv = S->cat[bb][i];
            float4 w = __ldg((const float4*)&W_out[i * 64 + j4]);
            acc.x += cv*w.x; acc.y += cv*w.y; acc.z += cv*w.z; acc.w += cv*w.w;
        }
        acc.x = acc.x > 0.f ? acc.x : 0.f;
        acc.y = acc.y > 0.f ? acc.y : 0.f;
        acc.z = acc.z > 0.f ? acc.z : 0.f;
        acc.w = acc.w > 0.f ? acc.w : 0.f;
        *(float4*)&out[(size_t)(b0 + bb) * 192 + 128 + j4] = acc;
    }
}

// ============================ launch ========================================
extern "C" void kernel_launch(void* const* d_in, const int* in_sizes, int n_in,
                              void* d_out, int out_size) {
    const float* self_f   = (const float*)d_in[0];
    const float* nbr_f    = (const float*)d_in[1];
    const float* mask     = (const float*)d_in[2];
    const float* dirs     = (const float*)d_in[3];
    const float* W_coop   = (const float*)d_in[4];
    const float* a_src_c  = (const float*)d_in[5];
    const float* a_dst_c  = (const float*)d_in[6];
    const float* W_conf   = (const float*)d_in[7];
    const float* a_src_f2 = (const float*)d_in[8];
    const float* a_dst_f2 = (const float*)d_in[9];
    const float* W_fuse   = (const float*)d_in[10];
    const float* b_fuse   = (const float*)d_in[11];
    const float* W_proj   = (const float*)d_in[12];
    const float* b_proj   = (const float*)d_in[13];
    const float* Wih_f    = (const float*)d_in[14];
    const float* Whh_f    = (const float*)d_in[15];
    const float* bih_f    = (const float*)d_in[16];
    const float* bhh_f    = (const float*)d_in[17];
    const float* Wih_b    = (const float*)d_in[18];
    const float* Whh_b    = (const float*)d_in[19];
    const float* bih_b    = (const float*)d_in[20];
    const float* bhh_b    = (const float*)d_in[21];
    const float* W_out    = (const float*)d_in[22];
    const float* b_out    = (const float*)d_in[23];
    float* out = (float*)d_out;

    cudaFuncSetAttribute(mgmq_fused, cudaFuncAttributeMaxDynamicSharedMemorySize, SMEM_FUSED);
    cudaFuncSetAttribute(mgmq_k2, cudaFuncAttributeMaxDynamicSharedMemorySize, SMEM_K2);

    mgmq_wsplit<<<128, 256>>>(W_fuse, W_coop, a_src_c, a_dst_c,
                              W_conf, a_src_f2, a_dst_f2);
    mgmq_fused<<<NTILES, 512, SMEM_FUSED>>>(self_f, nbr_f, W_coop, W_conf,
                                            b_fuse, out);
    mgmq_k2<<<NB / 8, 512, SMEM_K2>>>(mask, dirs, W_proj, b_proj,
                                      Wih_f, Whh_f, bih_f, bhh_f,
                                      Wih_b, Whh_b, bih_b, bhh_b,
                                      W_out, b_out, out);
}

// round 16
// speedup vs baseline: 1.0371x; 1.0371x over previous
#include <cuda_runtime.h>
#include <cuda_bf16.h>
#include <cstdint>

// ---------------------------------------------------------------------------
// MGMQTorchModel R16 (= R13 fused kernel + k2 with liveness-overlaid smem):
//   fused : GAT -> shuffle-pack bf16 hi/lo into smem A images (B kc0
//           prefetch overlapped) -> HMMA GEMM -> bias+elu+mean -> scatter.
//   k2    : R13 mapping (256 thr, 8 batches), smem 59KB -> 40.5KB via
//           phase-accurate region reuse (nbr -> gi -> cat).
// ---------------------------------------------------------------------------

#define NB 8192
#define NODES (NB*5)          // 40960
#define NTILES (NODES/8)      // 5120 (8 nodes x 12 rows = M 96)

__device__ float g_nbr_emb[NB * 4 * 128];
__device__ __nv_bfloat16 g_WtT[2 * 32768];   // [term][n 128][k 256]
__device__ float g_Wa[64];                   // [s][src/dst][h][f]

__device__ __forceinline__ float tanh_fast(float x) {
    float y; asm("tanh.approx.f32 %0, %1;" : "=f"(y) : "f"(x)); return y;
}
__device__ __forceinline__ float sigmoid_fast(float x) {
    return 1.f / (1.f + __expf(-x));
}
__device__ __forceinline__ float elu_f(float x) {
    return (x > 0.f) ? x : (__expf(x) - 1.f);
}
__device__ __forceinline__ uint32_t smem_u32(const void* p) {
    uint32_t a;
    asm("{ .reg .u64 t; cvta.to.shared.u64 t, %1; cvt.u32.u64 %0, t; }" : "=r"(a) : "l"(p));
    return a;
}
__device__ __forceinline__ void mma16816(float* d, const uint32_t* a,
                                         uint32_t b0, uint32_t b1) {
    asm volatile(
        "mma.sync.aligned.m16n8k16.row.col.f32.bf16.bf16.f32 "
        "{%0,%1,%2,%3}, {%4,%5,%6,%7}, {%8,%9}, {%0,%1,%2,%3};"
        : "+f"(d[0]), "+f"(d[1]), "+f"(d[2]), "+f"(d[3])
        : "r"(a[0]), "r"(a[1]), "r"(a[2]), "r"(a[3]), "r"(b0), "r"(b1));
}
#define LDSM_X4(r, addr) \
    asm volatile("ldmatrix.sync.aligned.m8n8.x4.shared.b16 {%0,%1,%2,%3}, [%4];" \
        : "=r"((r)[0]), "=r"((r)[1]), "=r"((r)[2]), "=r"((r)[3]) : "r"(addr))
#define GBAR(id) \
    asm volatile("bar.sync %0, 128;" :: "r"((id) + 1) : "memory")

// ======================= setup: W_fuse -> Wt images + Wa ====================
__global__ void mgmq_wsplit(const float* __restrict__ W_fuse,
                            const float* __restrict__ W_coop,
                            const float* __restrict__ a_src_coop,
                            const float* __restrict__ a_dst_coop,
                            const float* __restrict__ W_conf,
                            const float* __restrict__ a_src_conf,
                            const float* __restrict__ a_dst_conf) {
    int idx = blockIdx.x * blockDim.x + threadIdx.x;
    if (blockIdx.x == 0 && threadIdx.x < 64) {
        int i = threadIdx.x;
        int s = i >> 5, v = (i >> 4) & 1, h = (i >> 2) & 3, f = i & 3;
        const float* W = s ? W_conf : W_coop;
        const float* a = s ? (v ? a_dst_conf : a_src_conf)
                           : (v ? a_dst_coop : a_src_coop);
        float acc = 0.f;
        #pragma unroll
        for (int o = 0; o < 32; o++)
            acc += __ldg(&W[(h * 4 + f) * 32 + o]) * __ldg(&a[h * 32 + o]);
        g_Wa[i] = acc;
    }
    if (idx >= 128 * 256) return;
    int n = idx >> 8;
    int k = idx & 255;
    float w = W_fuse[k * 128 + n];
    __nv_bfloat16 hi = __float2bfloat16(w);
    __nv_bfloat16 lo = __float2bfloat16(w - __bfloat162float(hi));
    g_WtT[n * 256 + k] = hi;
    g_WtT[32768 + n * 256 + k] = lo;
}

// ======================== FUSED kernel (R13, unchanged) =====================
#define A_RS    528
#define AHI_OFF 0
#define ALO_OFF 50688
#define X_OFF   101376
#define B_IMG   34816
#define SW_OFF  171008
#define SX_OFF  175104
#define ATTC_OFF 176640
#define ATTF_OFF 179712
#define BIAS_OFF 188928
#define SMEM_FUSED 189440
#define CH_RS   272

__global__ __launch_bounds__(512) void mgmq_fused(
    const float* __restrict__ self_f, const float* __restrict__ nbr_f,
    const float* __restrict__ W_coop, const float* __restrict__ W_conf,
    const float* __restrict__ b_fuse, float* __restrict__ out)
{
    extern __shared__ char dsm[];
    float* sW   = (float*)(dsm + SW_OFF);
    float* sx   = (float*)(dsm + SX_OFF);
    float4* sAttC = (float4*)(dsm + ATTC_OFF);
    float*  sAttF = (float*)(dsm + ATTF_OFF);
    float* sbias = (float*)(dsm + BIAS_OFF);

    const int t = threadIdx.x;
    const int wid = t >> 5;
    const int lid = t & 31;
    const int tile = blockIdx.x;

    const uint4* gBH = (const uint4*)g_WtT;
    const uint4* gBL = (const uint4*)(g_WtT + 32768);

    if (t < 128) ((float4*)sW)[t] = __ldg(&((const float4*)W_coop)[t]);
    else if (t < 256) ((float4*)sW)[t] = __ldg(&((const float4*)W_conf)[t - 128]);
    if (t >= 384) sbias[t - 384] = __ldg(&b_fuse[t - 384]);
    if (t < 384) {
        int n8 = t / 48, f = t % 48;
        int node = tile * 8 + n8;
        int b = node / 5, slot = node - b * 5;
        const float* xsrc = (slot == 0) ? (self_f + (size_t)b * 48)
                                        : (nbr_f + ((size_t)b * 4 + (slot - 1)) * 48);
        sx[n8 * 48 + f] = __ldg(&xsrc[f]);
    }

    for (int i = t; i < 4096; i += 512) {
        int term = i >> 11;
        int r = i & 2047;
        int nr = r >> 4, c16 = r & 15;
        const uint4* gB = term ? gBL : gBH;
        *(uint4*)(dsm + X_OFF + term * B_IMG + nr * CH_RS + c16 * 16)
            = gB[nr * 32 + c16];
    }
    __syncthreads();

    const int nl = t >> 7;
    const int tt = t & 127;
    const int o = tt & 31, h = tt >> 5;
    const int opair2 = (o & ~1) * 2;
    const bool evn = (o & 1) == 0;

    #pragma unroll
    for (int p = 0; p < 2; p++) {
        const int n8 = p * 4 + nl;
        const float* nx = sx + n8 * 48;

        if (tt < 48) {
            int hh = tt / 12, i = tt - hh * 12, j0 = (i / 3) * 3;
            float was0 = __ldg(&g_Wa[hh*4+0]), was1 = __ldg(&g_Wa[hh*4+1]);
            float was2 = __ldg(&g_Wa[hh*4+2]), was3 = __ldg(&g_Wa[hh*4+3]);
            float wad0 = __ldg(&g_Wa[16+hh*4+0]), wad1 = __ldg(&g_Wa[16+hh*4+1]);
            float wad2 = __ldg(&g_Wa[16+hh*4+2]), wad3 = __ldg(&g_Wa[16+hh*4+3]);
            float es = nx[i*4]*was0 + nx[i*4+1]*was1 + nx[i*4+2]*was2 + nx[i*4+3]*was3;
            float e[3];
            #pragma unroll
            for (int jj = 0; jj < 3; jj++) {
                int j = j0 + jj;
                float ed = nx[j*4]*wad0 + nx[j*4+1]*wad1 + nx[j*4+2]*wad2 + nx[j*4+3]*wad3;
                float v = es + ed;
                e[jj] = (v > 0.f) ? v : 0.2f * v;
            }
            float m = fmaxf(e[0], fmaxf(e[1], e[2]));
            float x0 = __expf(e[0]-m), x1 = __expf(e[1]-m), x2 = __expf(e[2]-m);
            float inv = 1.f / (x0 + x1 + x2);
            sAttC[(nl * 4 + hh) * 12 + i] = make_float4(x0*inv, x1*inv, x2*inv, 0.f);
        } else if (tt < 96) {
            int r = tt - 48;
            int hh = r / 12, i = r - hh * 12;
            int gi = i / 3;
            float was0 = __ldg(&g_Wa[32+hh*4+0]), was1 = __ldg(&g_Wa[32+hh*4+1]);
            float was2 = __ldg(&g_Wa[32+hh*4+2]), was3 = __ldg(&g_Wa[32+hh*4+3]);
            float wad0 = __ldg(&g_Wa[48+hh*4+0]), wad1 = __ldg(&g_Wa[48+hh*4+1]);
            float wad2 = __ldg(&g_Wa[48+hh*4+2]), wad3 = __ldg(&g_Wa[48+hh*4+3]);
            float es = nx[i*4]*was0 + nx[i*4+1]*was1 + nx[i*4+2]*was2 + nx[i*4+3]*was3;
            float ev[12], m = -1e30f;
            #pragma unroll
            for (int j = 0; j < 12; j++) {
                float ed = nx[j*4]*wad0 + nx[j*4+1]*wad1 + nx[j*4+2]*wad2 + nx[j*4+3]*wad3;
                float e = es + ed;
                e = (e > 0.f) ? e : 0.2f * e;
                bool valid = ((j / 3) != gi);
                ev[j] = valid ? e : -1e30f;
                if (valid && e > m) m = e;
            }
            float sum = 0.f, ex[12];
            #pragma unroll
            for (int j = 0; j < 12; j++) {
                float v = (ev[j] > -1e29f) ? __expf(ev[j] - m) : 0.f;
                ex[j] = v; sum += v;
            }
            float inv = 1.f / sum;
            #pragma unroll
            for (int j = 0; j < 12; j++)
                sAttF[((nl * 4 + hh) * 12 + i) * 12 + j] = ex[j] * inv;
        }

        float wh0[12], wh1[12];
        {
            float w00 = sW[h*128 +  0 + o], w01 = sW[h*128 + 32 + o];
            float w02 = sW[h*128 + 64 + o], w03 = sW[h*128 + 96 + o];
            float w10 = sW[512 + h*128 +  0 + o], w11 = sW[512 + h*128 + 32 + o];
            float w12 = sW[512 + h*128 + 64 + o], w13 = sW[512 + h*128 + 96 + o];
            #pragma unroll
            for (int j = 0; j < 12; j++) {
                float x0 = nx[j*4], x1 = nx[j*4+1], x2 = nx[j*4+2], x3 = nx[j*4+3];
                wh0[j] = x0*w00 + x1*w01 + x2*w02 + x3*w03;
                wh1[j] = x0*w10 + x1*w11 + x2*w12 + x3*w13;
            }
        }
        GBAR(nl);

        {
            const int rbase = n8 * 12;
            #pragma unroll
            for (int i = 0; i < 12; i++) {
                const int j0 = (i / 3) * 3;
                float4 a = sAttC[(nl * 4 + h) * 12 + i];
                float vc = elu_f(a.x * wh0[j0] + a.y * wh0[j0+1] + a.z * wh0[j0+2]);
                const float* ar = sAttF + ((nl * 4 + h) * 12 + i) * 12;
                float accf = 0.f;
                #pragma unroll
                for (int j = 0; j < 12; j++)
                    if (j < j0 || j >= j0 + 3) accf += ar[j] * wh1[j];
                float vf = elu_f(accf);

                const uint32_t rowoff = (uint32_t)(rbase + i) * A_RS;
                {
                    __nv_bfloat16 hb = __float2bfloat16(vc);
                    float rr = vc - __bfloat162float(hb);
                    __nv_bfloat16 lb = __float2bfloat16(rr);
                    uint32_t hu = (uint32_t)__bfloat16_as_ushort(hb);
                    uint32_t lu = (uint32_t)__bfloat16_as_ushort(lb);
                    uint32_t ho = __shfl_xor_sync(0xFFFFFFFFu, hu, 1);
                    uint32_t lo = __shfl_xor_sync(0xFFFFFFFFu, lu, 1);
                    uint32_t boff = rowoff + (uint32_t)(h * 64) + opair2;
                    if (evn) *(uint32_t*)(dsm + AHI_OFF + boff) = hu | (ho << 16);
                    else     *(uint32_t*)(dsm + ALO_OFF + boff) = lo | (lu << 16);
                }
                {
                    __nv_bfloat16 hb = __float2bfloat16(vf);
                    float rr = vf - __bfloat162float(hb);
                    __nv_bfloat16 lb = __float2bfloat16(rr);
                    uint32_t hu = (uint32_t)__bfloat16_as_ushort(hb);
                    uint32_t lu = (uint32_t)__bfloat16_as_ushort(lb);
                    uint32_t ho = __shfl_xor_sync(0xFFFFFFFFu, hu, 1);
                    uint32_t lo = __shfl_xor_sync(0xFFFFFFFFu, lu, 1);
                    uint32_t boff = rowoff + 256u + (uint32_t)(h * 64) + opair2;
                    if (evn) *(uint32_t*)(dsm + AHI_OFF + boff) = hu | (ho << 16);
                    else     *(uint32_t*)(dsm + ALO_OFF + boff) = lo | (lu << 16);
                }
            }
        }
        GBAR(nl);
    }
    __syncthreads();

    const int mtile = wid >> 1;
    const int nhalf = wid & 1;
    const int g = lid >> 2;
    const int q = lid & 3;
    const int row0 = mtile * 16 + g;
    const int row1 = row0 + 8;
    const bool mma_w = (wid < 12);

    const uint32_t sbase = smem_u32(dsm);
    const uint32_t a_lane = (uint32_t)((mtile * 16 + ((lid >> 3) & 1) * 8 + (lid & 7)) * A_RS
                          + ((lid >> 4) & 1) * 16);
    const uint32_t b_lane = (uint32_t)((nhalf * 64 + ((lid >> 4) & 1) * 8 + (lid & 7)) * CH_RS
                          + ((lid >> 3) & 1) * 16);

    float d[8][4];
    #pragma unroll
    for (int nt = 0; nt < 8; nt++) {
        d[nt][0] = 0.f; d[nt][1] = 0.f; d[nt][2] = 0.f; d[nt][3] = 0.f;
    }

    #pragma unroll
    for (int kc = 0; kc < 2; kc++) {
        if (kc == 1) {
            for (int i = t; i < 4096; i += 512) {
                int term = i >> 11;
                int r = i & 2047;
                int nr = r >> 4, c16 = r & 15;
                const uint4* gB = term ? gBL : gBH;
                *(uint4*)(dsm + X_OFF + term * B_IMG + nr * CH_RS + c16 * 16)
                    = gB[nr * 32 + 16 + c16];
            }
            __syncthreads();
        }

        if (mma_w) {
            const uint32_t aHb = sbase + AHI_OFF + a_lane + kc * 256;
            const uint32_t aLb = sbase + ALO_OFF + a_lane + kc * 256;
            const uint32_t bHb = sbase + X_OFF + b_lane;
            const uint32_t bLb = sbase + X_OFF + B_IMG + b_lane;

            #pragma unroll
            for (int ks = 0; ks < 8; ks++) {
                const uint32_t koff = ks * 32;
                uint32_t ah[4], al[4];
                LDSM_X4(ah, aHb + koff);
                LDSM_X4(al, aLb + koff);
                #pragma unroll
                for (int pp = 0; pp < 4; pp++) {
                    uint32_t bh[4], bl[4];
                    LDSM_X4(bh, bHb + pp * (16 * CH_RS) + koff);
                    LDSM_X4(bl, bLb + pp * (16 * CH_RS) + koff);
                    mma16816(d[2*pp],     ah, bh[0], bh[1]);
                    mma16816(d[2*pp],     ah, bl[0], bl[1]);
                    mma16816(d[2*pp],     al, bh[0], bh[1]);
                    mma16816(d[2*pp + 1], ah, bh[2], bh[3]);
                    mma16816(d[2*pp + 1], ah, bl[2], bl[3]);
                    mma16816(d[2*pp + 1], al, bh[2], bh[3]);
                }
            }
        }
        __syncthreads();
    }

    float* Dbuf = (float*)(dsm + X_OFF);
    if (mma_w) {
        #pragma unroll
        for (int nt = 0; nt < 8; nt++) {
            int c0 = nhalf * 64 + nt * 8 + q * 2;
            float b0 = sbias[c0], b1 = sbias[c0 + 1];
            float2 v0 = make_float2(elu_f(d[nt][0] + b0), elu_f(d[nt][1] + b1));
            float2 v1 = make_float2(elu_f(d[nt][2] + b0), elu_f(d[nt][3] + b1));
            *(float2*)&Dbuf[row0 * 132 + c0] = v0;
            *(float2*)&Dbuf[row1 * 132 + c0] = v1;
        }
    }
    __syncthreads();

    if (t < 256) {
        int nl8 = t >> 5;
        int c4 = (t & 31) << 2;
        float4 s = make_float4(0.f, 0.f, 0.f, 0.f);
        #pragma unroll
        for (int j = 0; j < 12; j++) {
            float4 v = *(const float4*)&Dbuf[(nl8 * 12 + j) * 132 + c4];
            s.x += v.x; s.y += v.y; s.z += v.z; s.w += v.w;
        }
        s.x *= (1.f/12.f); s.y *= (1.f/12.f); s.z *= (1.f/12.f); s.w *= (1.f/12.f);
        int node = tile * 8 + nl8;
        int b = node / 5, slot = node - b * 5;
        if (slot == 0) *(float4*)&out[(size_t)b * 192 + c4] = s;
        else *(float4*)&g_nbr_emb[((size_t)b * 4 + (slot - 1)) * 128 + c4] = s;
    }
}

// ============================ KERNEL 2 ======================================
// R13 mapping, liveness-overlaid smem:
//   x   @0      (8192)
//   nbr @8192   (16896)  phase 1 only
//   gi  @8192   (24576)  written after proj (nbr dead)
//   gh  @33280  (6144)
//   h   @39424  (2048)
//   cat @8192   (6144)   written after GRU (gi dead)
// total 41472 B -> 5 CTAs/SM
#define K2_X_O   0
#define K2_NBR_O 8192
#define K2_GI_O  8192
#define K2_GH_O  33280
#define K2_H_O   39424
#define K2_CAT_O 8192
#define SMEM_K2  41472

__global__ __launch_bounds__(256) void mgmq_k2(
    const float* __restrict__ mask, const float* __restrict__ dirs,
    const float* __restrict__ W_proj, const float* __restrict__ b_proj,
    const float* __restrict__ Wih_f, const float* __restrict__ Whh_f,
    const float* __restrict__ bih_f, const float* __restrict__ bhh_f,
    const float* __restrict__ Wih_b, const float* __restrict__ Whh_b,
    const float* __restrict__ bih_b, const float* __restrict__ bhh_b,
    const float* __restrict__ W_out, const float* __restrict__ b_out,
    float* __restrict__ out)
{
    extern __shared__ char k2dsm[];
    float (*Sx)[4][64]      = (float(*)[4][64])     (k2dsm + K2_X_O);
    float (*Snbr)[4][132]   = (float(*)[4][132])    (k2dsm + K2_NBR_O);
    float (*Sgi)[2][4][96]  = (float(*)[2][4][96])  (k2dsm + K2_GI_O);
    float (*Sgh)[2][96]     = (float(*)[2][96])     (k2dsm + K2_GH_O);
    float (*Sh)[2][32]      = (float(*)[2][32])     (k2dsm + K2_H_O);
    float (*Scat)[192]      = (float(*)[192])       (k2dsm + K2_CAT_O);

    const int b0 = blockIdx.x * 8;
    const int t = threadIdx.x;

    // ---- phase 1: load nbr(+dirs), init h ----
    for (int i = t; i < 1024; i += 256) {
        int bb = i >> 7, kk = (i >> 5) & 3, c4 = (i & 31) << 2;
        *(float4*)&Snbr[bb][kk][c4] =
            *(const float4*)&g_nbr_emb[(((size_t)(b0 + bb)) * 4 + kk) * 128 + c4];
    }
    if (t < 32) Snbr[t >> 2][t & 3][128] = dirs[(b0 + (t >> 2)) * 4 + (t & 3)];
    if (t < 128) {
        int bb = t >> 4, d = (t >> 3) & 1, g8 = (t & 7) << 2;
        *(float4*)&Sh[bb][d][g8] = make_float4(0.f, 0.f, 0.f, 0.f);
    }
    __syncthreads();

    // ---- proj: 64 combos x 4 groups, 2 batches per thread (R13 mapping) ----
    {
        int combo = t & 63, grp = t >> 6;
        int kk = combo >> 4, j4 = (combo & 15) << 2;
        int bA = grp, bB = grp + 4;
        float4 bs = __ldg((const float4*)&b_proj[j4]);
        float4 a0 = bs, a1 = bs;
        #pragma unroll 4
        for (int i = 0; i < 129; i++) {
            float4 w = __ldg((const float4*)&W_proj[i * 64 + j4]);
            float x0 = Snbr[bA][kk][i], x1 = Snbr[bB][kk][i];
            a0.x += x0*w.x; a0.y += x0*w.y; a0.z += x0*w.z; a0.w += x0*w.w;
            a1.x += x1*w.x; a1.y += x1*w.y; a1.z += x1*w.z; a1.w += x1*w.w;
        }
        float m0 = mask[(b0 + bA) * 4 + kk], m1 = mask[(b0 + bB) * 4 + kk];
        a0.x = (a0.x > 0.f ? a0.x : 0.f) * m0; a0.y = (a0.y > 0.f ? a0.y : 0.f) * m0;
        a0.z = (a0.z > 0.f ? a0.z : 0.f) * m0; a0.w = (a0.w > 0.f ? a0.w : 0.f) * m0;
        a1.x = (a1.x > 0.f ? a1.x : 0.f) * m1; a1.y = (a1.y > 0.f ? a1.y : 0.f) * m1;
        a1.z = (a1.z > 0.f ? a1.z : 0.f) * m1; a1.w = (a1.w > 0.f ? a1.w : 0.f) * m1;
        *(float4*)&Sx[bA][kk][j4] = a0;
        *(float4*)&Sx[bB][kk][j4] = a1;
    }
    __syncthreads();   // proj done; nbr dead -> gi may overwrite

    // ---- gi: 192 threads, 8 batches each (R13 mapping) ----
    if (t < 192) {
        int d = t / 96, r = t % 96, kk = r / 24, j4 = (r % 24) << 2;
        const float* Wih = d ? Wih_b : Wih_f;
        const float* bih = d ? bih_b : bih_f;
        float4 bs = __ldg((const float4*)&bih[j4]);
        float4 acc[8];
        #pragma unroll
        for (int bb = 0; bb < 8; bb++) acc[bb] = bs;
        for (int i = 0; i < 64; i++) {
            float4 w = __ldg((const float4*)&Wih[i * 96 + j4]);
            #pragma unroll
            for (int bb = 0; bb < 8; bb++) {
                float xv = Sx[bb][kk][i];
                acc[bb].x += xv*w.x; acc[bb].y += xv*w.y;
                acc[bb].z += xv*w.z; acc[bb].w += xv*w.w;
            }
        }
        #pragma unroll
        for (int bb = 0; bb < 8; bb++) *(float4*)&Sgi[bb][d][kk][j4] = acc[bb];
    }
    __syncthreads();

    // ---- GRU: 4 steps (R13 mapping) ----
    for (int step = 0; step < 4; step++) {
        if (t < 192) {
            int combo = t % 48, grp = t / 48;
            int d = combo / 24, j4 = (combo % 24) << 2;
            int bA = grp, bB = grp + 4;
            const float* Whh = d ? Whh_b : Whh_f;
            const float* bhh = d ? bhh_b : bhh_f;
            float4 bs = __ldg((const float4*)&bhh[j4]);
            float4 a0 = bs, a1 = bs;
            #pragma unroll
            for (int i = 0; i < 32; i++) {
                float4 w = __ldg((const float4*)&Whh[i * 96 + j4]);
                float h0 = Sh[bA][d][i], h1 = Sh[bB][d][i];
                a0.x += h0*w.x; a0.y += h0*w.y; a0.z += h0*w.z; a0.w += h0*w.w;
                a1.x += h1*w.x; a1.y += h1*w.y; a1.z += h1*w.z; a1.w += h1*w.w;
            }
            *(float4*)&Sgh[bA][d][j4] = a0;
            *(float4*)&Sgh[bB][d][j4] = a1;
        }
        __syncthreads();
        {
            int bA = t >> 6, d = (t >> 5) & 1, g = t & 31;
            #pragma unroll
            for (int p = 0; p < 2; p++) {
                int bb = bA + p * 4;
                int kf = d ? (3 - step) : step;
                float r = sigmoid_fast(Sgi[bb][d][kf][g]      + Sgh[bb][d][g]);
                float z = sigmoid_fast(Sgi[bb][d][kf][32 + g] + Sgh[bb][d][32 + g]);
                float nn = tanh_fast(Sgi[bb][d][kf][64 + g] + r * Sgh[bb][d][64 + g]);
                Sh[bb][d][g] = (1.f - z) * nn + z * Sh[bb][d][g];
            }
        }
        __syncthreads();
    }
    // gi dead from here; cat overlays it

    // ---- build cat: self_emb (global) + h ----
    for (int i = t; i < 512; i += 256) {
        int bb = i >> 6, c4 = (i & 63) << 1;  // 8bb x 64 -> cover 128 floats via 2-wide
        *(float2*)&Scat[bb][c4] =
            *(const float2*)&out[(size_t)(b0 + bb) * 192 + c4];
    }
    for (int i = t; i < 512; i += 256) {
        int bb = i >> 6, r = i & 63;
        Scat[bb][128 + r] = Sh[bb][r >> 5][r & 31];
    }
    __syncthreads();

    // ---- out GEMV ----
    if (t < 128) {
        int bb = t >> 4, j4 = (t & 15) << 2;
        float4 acc = __ldg((const float4*)&b_out[j4]);
        #pragma unroll 4
        for (int i = 0; i < 192; i++) {
            float cv = Scat[bb][i];
            float4 w = __ldg((const float4*)&W_out[i * 64 + j4]);
            acc.x += cv*w.x; acc.y += cv*w.y; acc.z += cv*w.z; acc.w += cv*w.w;
        }
        acc.x = acc.x > 0.f ? acc.x : 0.f;
        acc.y = acc.y > 0.f ? acc.y : 0.f;
        acc.z = acc.z > 0.f ? acc.z : 0.f;
        acc.w = acc.w > 0.f ? acc.w : 0.f;
        *(float4*)&out[(size_t)(b0 + bb) * 192 + 128 + j4] = acc;
    }
}

// ============================ launch ========================================
extern "C" void kernel_launch(void* const* d_in, const int* in_sizes, int n_in,
                              void* d_out, int out_size) {
    const float* self_f   = (const float*)d_in[0];
    const float* nbr_f    = (const float*)d_in[1];
    const float* mask     = (const float*)d_in[2];
    const float* dirs     = (const float*)d_in[3];
    const float* W_coop   = (const float*)d_in[4];
    const float* a_src_c  = (const float*)d_in[5];
    const float* a_dst_c  = (const float*)d_in[6];
    const float* W_conf   = (const float*)d_in[7];
    const float* a_src_f2 = (const float*)d_in[8];
    const float* a_dst_f2 = (const float*)d_in[9];
    const float* W_fuse   = (const float*)d_in[10];
    const float* b_fuse   = (const float*)d_in[11];
    const float* W_proj   = (const float*)d_in[12];
    const float* b_proj   = (const float*)d_in[13];
    const float* Wih_f    = (const float*)d_in[14];
    const float* Whh_f    = (const float*)d_in[15];
    const float* bih_f    = (const float*)d_in[16];
    const float* bhh_f    = (const float*)d_in[17];
    const float* Wih_b    = (const float*)d_in[18];
    const float* Whh_b    = (const float*)d_in[19];
    const float* bih_b    = (const float*)d_in[20];
    const float* bhh_b    = (const float*)d_in[21];
    const float* W_out    = (const float*)d_in[22];
    const float* b_out    = (const float*)d_in[23];
    float* out = (float*)d_out;

    cudaFuncSetAttribute(mgmq_fused, cudaFuncAttributeMaxDynamicSharedMemorySize, SMEM_FUSED);
    cudaFuncSetAttribute(mgmq_k2, cudaFuncAttributeMaxDynamicSharedMemorySize, SMEM_K2);

    mgmq_wsplit<<<128, 256>>>(W_fuse, W_coop, a_src_c, a_dst_c,
                              W_conf, a_src_f2, a_dst_f2);
    mgmq_fused<<<NTILES, 512, SMEM_FUSED>>>(self_f, nbr_f, W_coop, W_conf,
                                            b_fuse, out);
    mgmq_k2<<<NB / 8, 256, SMEM_K2>>>(mask, dirs, W_proj, b_proj,
                                      Wih_f, Whh_f, bih_f, bhh_f,
                                      Wih_b, Whh_b, bih_b, bhh_b,
                                      W_out, b_out, out);
}